// round 5
// baseline (speedup 1.0000x reference)
#include <cuda_runtime.h>
#include <cuda_fp16.h>

// ---------------- problem constants ----------------
#define NBATCH 65536
#define NNODE  10
#define KD     512
#define HD     64
#define NC     128
#define MROWS  (NBATCH * NNODE)            // 655360
#define BPC    12                          // batches per tile
#define RPC    120                         // valid rows per tile
#define NCTA   ((NBATCH + BPC - 1) / BPC)  // 5462 tiles
#define GRID   148                         // persistent CTAs (1/SM)

__constant__ int c_I[45] = {0,0,0,0,0,0,0,0,0, 1,1,1,1,1,1,1,1, 2,2,2,2,2,2,2,
                            3,3,3,3,3,3, 4,4,4,4,4, 5,5,5,5, 6,6,6, 7,7, 8};
__constant__ int c_J[45] = {1,2,3,4,5,6,7,8,9, 2,3,4,5,6,7,8,9, 3,4,5,6,7,8,9,
                            4,5,6,7,8,9, 5,6,7,8,9, 6,7,8,9, 7,8,9, 8,9, 9};

// ---------------- smem layout ----------------
// [0:256)    sb1 (f32 x64)
// [256:512)  sw2 (f32 x64)
// [512:516)  b2
// [1024: +139264) B fp16 [512 rows][136 halves] (272B row stride, 16B-step banks)
// [OFF_SP: +66560) sp f32 [128][130]   (epilogue P tile)
// [OFF_VBUF: +2160) vbuf f32 [540]
#define OFF_SB1   0
#define OFF_SW2   256
#define OFF_SB2   512
#define OFF_B     1024
#define BROW      272                       // bytes per B row
#define B_BYTES   (KD * BROW)               // 139264
#define OFF_SP    (OFF_B + B_BYTES)         // 140288
#define SP_STRIDE 130
#define OFF_VBUF  (OFF_SP + 128 * SP_STRIDE * 4)   // 206848
#define SMEM_BYTES (OFF_VBUF + 540 * 4 + 16)       // 209024

__device__ __forceinline__ unsigned smem_u32(const void* p) {
    unsigned a;
    asm("{ .reg .u64 t; cvta.to.shared.u64 t, %1; cvt.u32.u64 %0, t; }" : "=r"(a) : "l"(p));
    return a;
}

#define LDMX4T(r0, r1, r2, r3, addr) \
    asm volatile("ldmatrix.sync.aligned.m8n8.x4.trans.shared.b16 {%0,%1,%2,%3}, [%4];" \
                 : "=r"(r0), "=r"(r1), "=r"(r2), "=r"(r3) : "r"(addr))

#define MMA16816(d, a0, a1, a2, a3, b0, b1) \
    asm volatile("mma.sync.aligned.m16n8k16.row.col.f32.f16.f16.f32 " \
                 "{%0,%1,%2,%3},{%4,%5,%6,%7},{%8,%9},{%0,%1,%2,%3};" \
                 : "+f"((d)[0]), "+f"((d)[1]), "+f"((d)[2]), "+f"((d)[3]) \
                 : "r"(a0), "r"(a1), "r"(a2), "r"(a3), "r"(b0), "r"(b1))

// ---------------- fused persistent kernel ----------------
__global__ __launch_bounds__(256)
void fused_kernel(const float* __restrict__ X, const float* __restrict__ W1,
                  const float* __restrict__ b1, const float* __restrict__ W2,
                  const float* __restrict__ b2, float* __restrict__ out) {
    extern __shared__ char smem[];
    const unsigned sb = smem_u32(smem);
    const int tid  = threadIdx.x;
    const int warp = tid >> 5;
    const int lane = tid & 31;
    const int wm   = warp & 3;      // M group (4)
    const int wn   = warp >> 2;     // N group (2)
    const int gid  = lane >> 2;     // 0..7
    const int tig  = lane & 3;      // 0..3

    // ---- prologue: consts + full B (W1 -> fp16 [k][n], n-contiguous) ----
    if (tid < HD) {
        ((float*)(smem + OFF_SB1))[tid] = b1[tid];
        ((float*)(smem + OFF_SW2))[tid] = W2[tid];
    }
    if (tid == 0) ((float*)(smem + OFF_SB2))[0] = b2[0];

    #pragma unroll 4
    for (int base = tid * 4; base < KD * NC; base += 1024) {
        int k = base >> 7, n = base & 127;
        const float4 w4 = *(const float4*)(W1 + (size_t)((n >= HD) ? k + KD : k) * HD + (n & 63));
        __half2 h0 = __floats2half2_rn(w4.x, w4.y);
        __half2 h1 = __floats2half2_rn(w4.z, w4.w);
        unsigned u0 = *(unsigned*)&h0, u1 = *(unsigned*)&h1;
        asm volatile("st.shared.v2.b32 [%0], {%1,%2};"
                     :: "r"(sb + OFF_B + k * BROW + n * 2), "r"(u0), "r"(u1) : "memory");
    }
    __syncthreads();

    // ldmatrix lane-constant address part
    const unsigned sel   = lane >> 3;          // which 8x8 matrix
    const unsigned rowin = lane & 7;
    const unsigned ldm0  = sb + OFF_B + ((sel & 1) * 8 + rowin) * BROW
                           + (wn * 64 + (sel >> 1) * 8) * 2;

    float* sp   = (float*)(smem + OFF_SP);
    float* vbuf = (float*)(smem + OFF_VBUF);
    const float* ssb1 = (const float*)(smem + OFF_SB1);
    const float* ssw2 = (const float*)(smem + OFF_SW2);
    const float bias2 = ((const float*)(smem + OFF_SB2))[0];

    // A fragment row pointers (4 rows per thread), recomputed per tile
    const float* xp[4];
    float2 Abuf[8];

    auto setup_tile = [&](int t) {
        long long r0 = (long long)t * RPC + wm * 32 + gid;
        #pragma unroll
        for (int q = 0; q < 4; q++) {
            long long rr = r0 + q * 8;
            if (rr >= MROWS) rr = MROWS - 1;
            xp[q] = X + rr * KD;
        }
    };
    auto loadA = [&](int h) {   // load 16-k half 'h' (0..31) into Abuf
        const int cb = h * 16 + 2 * tig;
        #pragma unroll
        for (int i = 0; i < 2; i++) {
            Abuf[i * 4 + 0] = *(const float2*)(xp[i * 2]     + cb);
            Abuf[i * 4 + 1] = *(const float2*)(xp[i * 2 + 1] + cb);
            Abuf[i * 4 + 2] = *(const float2*)(xp[i * 2]     + cb + 8);
            Abuf[i * 4 + 3] = *(const float2*)(xp[i * 2 + 1] + cb + 8);
        }
    };

    int tile = blockIdx.x;
    if (tile < NCTA) { setup_tile(tile); loadA(0); }

    while (tile < NCTA) {
        float acc[2][8][4];
        #pragma unroll
        for (int i = 0; i < 2; i++)
            #pragma unroll
            for (int j = 0; j < 8; j++)
                #pragma unroll
                for (int q = 0; q < 4; q++) acc[i][j][q] = 0.0f;

        // ---- GEMM main loop: 32 halves of k=16, no CTA syncs ----
        #pragma unroll 1
        for (int h = 0; h < 32; ++h) {
            // convert current A half to fragment regs
            unsigned Ar[8];
            #pragma unroll
            for (int q = 0; q < 8; q++) {
                __half2 t = __floats2half2_rn(Abuf[q].x, Abuf[q].y);
                Ar[q] = *(unsigned*)&t;
            }
            if (h < 31) loadA(h + 1);   // prefetch next half

            // B fragments for this half: 4x ldmatrix.x4.trans -> 8 n8 frags
            unsigned bfr[16];
            const unsigned ab = ldm0 + (unsigned)h * (16 * BROW);
            #pragma unroll
            for (int jj = 0; jj < 4; jj++)
                LDMX4T(bfr[jj * 4 + 0], bfr[jj * 4 + 1], bfr[jj * 4 + 2], bfr[jj * 4 + 3],
                       ab + jj * 32);

            #pragma unroll
            for (int i = 0; i < 2; i++)
                #pragma unroll
                for (int j = 0; j < 8; j++)
                    MMA16816(acc[i][j], Ar[i * 4 + 0], Ar[i * 4 + 1], Ar[i * 4 + 2], Ar[i * 4 + 3],
                             bfr[2 * j], bfr[2 * j + 1]);
        }

        // prefetch next tile's first A half during epilogue
        const int ntile = tile + GRID;
        if (ntile < NCTA) { setup_tile(ntile); loadA(0); }

        // ---- epilogue: acc -> sp ----
        #pragma unroll
        for (int i = 0; i < 2; i++)
            #pragma unroll
            for (int j = 0; j < 8; j++) {
                int r = wm * 32 + i * 16 + gid;
                int c = wn * 64 + j * 8 + 2 * tig;
                *(float2*)(sp + r * SP_STRIDE + c)       = make_float2(acc[i][j][0], acc[i][j][1]);
                *(float2*)(sp + (r + 8) * SP_STRIDE + c) = make_float2(acc[i][j][2], acc[i][j][3]);
            }
        __syncthreads();

        // ---- pair compute ----
        const int nb = (int)min((long long)BPC, (long long)NBATCH - (long long)tile * BPC);
        for (int p = tid; p < nb * 45; p += 256) {
            int bb = p / 45, q = p - bb * 45;
            const float* pi = sp + (bb * NNODE + c_I[q]) * SP_STRIDE;        // pa row
            const float* pj = sp + (bb * NNODE + c_J[q]) * SP_STRIDE + HD;   // pb row
            float a2 = 0.0f;
            #pragma unroll
            for (int h = 0; h < HD; h++)
                a2 = fmaf(fmaxf(pi[h] + pj[h] + ssb1[h], 0.0f), ssw2[h], a2);
            vbuf[p] = a2 + bias2;
        }
        __syncthreads();

        // ---- symmetric scatter ----
        for (int o = tid; o < nb * 100; o += 256) {
            int bb = o / 100, cell = o - bb * 100;
            int n1 = cell / 10, n2 = cell % 10;
            float val = 0.0f;
            if (n1 != n2) {
                int i = n1 < n2 ? n1 : n2;
                int j = n1 < n2 ? n2 : n1;
                val = vbuf[bb * 45 + 9 * i - (i * (i - 1)) / 2 + (j - i - 1)];
            }
            out[((long long)tile * BPC + bb) * 100 + cell] = val;
        }
        tile = ntile;
    }
}

extern "C" void kernel_launch(void* const* d_in, const int* in_sizes, int n_in,
                              void* d_out, int out_size) {
    const float* X  = (const float*)d_in[0];
    const float* W1 = (const float*)d_in[1];
    const float* b1 = (const float*)d_in[2];
    const float* W2 = (const float*)d_in[3];
    const float* b2 = (const float*)d_in[4];
    float* out = (float*)d_out;

    cudaFuncSetAttribute(fused_kernel,
                         cudaFuncAttributeMaxDynamicSharedMemorySize, SMEM_BYTES);
    fused_kernel<<<GRID, 256, SMEM_BYTES>>>(X, W1, b1, W2, b2, out);
}

// round 6
// speedup vs baseline: 1.5589x; 1.5589x over previous
#include <cuda_runtime.h>
#include <cuda_fp16.h>

// ---------------- problem constants ----------------
#define NBATCH 65536
#define NNODE  10
#define KD     512
#define HD     64
#define NC     128
#define MROWS  (NBATCH * NNODE)            // 655360
#define BPC    12                          // batches per CTA
#define RPC    120                         // valid rows per CTA
#define NCTA   ((NBATCH + BPC - 1) / BPC)  // 5462
#define NCHUNK 16                          // K chunks of 32

// W1 -> fp16, layout [k_phys][n] with k-permutation baked in (see convB).
__device__ __align__(128) __half g_Bh[KD * NC];

__constant__ int c_I[45] = {0,0,0,0,0,0,0,0,0, 1,1,1,1,1,1,1,1, 2,2,2,2,2,2,2,
                            3,3,3,3,3,3, 4,4,4,4,4, 5,5,5,5, 6,6,6, 7,7, 8};
__constant__ int c_J[45] = {1,2,3,4,5,6,7,8,9, 2,3,4,5,6,7,8,9, 3,4,5,6,7,8,9,
                            4,5,6,7,8,9, 5,6,7,8,9, 6,7,8,9, 7,8,9, 8,9, 9};

// ---------------- smem layout ----------------
// [0:256) sb1 ; [256:512) sw2 ; [512:516) b2
// [1024 : +2*8704)  B stages: [32 rows][272B] fp16 each
// [OFF_SP : +66560) sp f32 [128][130]
// [OFF_VBUF : +2160) vbuf f32 [540]
#define OFF_SB1   0
#define OFF_SW2   256
#define OFF_SB2   512
#define OFF_BSTG  1024
#define BROW      272
#define STAGE_SZ  (32 * BROW)              // 8704
#define OFF_SP    (OFF_BSTG + 2 * STAGE_SZ)       // 18432
#define SP_STRIDE 130
#define OFF_VBUF  (OFF_SP + 128 * SP_STRIDE * 4)  // 84992
#define SMEM_BYTES (OFF_VBUF + 540 * 4 + 16)      // 87168

__device__ __forceinline__ unsigned smem_u32(const void* p) {
    unsigned a;
    asm("{ .reg .u64 t; cvta.to.shared.u64 t, %1; cvt.u32.u64 %0, t; }" : "=r"(a) : "l"(p));
    return a;
}
__device__ __forceinline__ void cp16(unsigned dst, const void* src) {
    asm volatile("cp.async.cg.shared.global [%0], [%1], 16;" :: "r"(dst), "l"(src) : "memory");
}
#define CP_COMMIT() asm volatile("cp.async.commit_group;" ::: "memory")
#define CP_WAIT0()  asm volatile("cp.async.wait_group 0;" ::: "memory")

#define LDMX4T(r0, r1, r2, r3, addr) \
    asm volatile("ldmatrix.sync.aligned.m8n8.x4.trans.shared.b16 {%0,%1,%2,%3}, [%4];" \
                 : "=r"(r0), "=r"(r1), "=r"(r2), "=r"(r3) : "r"(addr))

#define MMA16816(d, a0, a1, a2, a3, b0, b1) \
    asm volatile("mma.sync.aligned.m16n8k16.row.col.f32.f16.f16.f32 " \
                 "{%0,%1,%2,%3},{%4,%5,%6,%7},{%8,%9},{%0,%1,%2,%3};" \
                 : "+f"((d)[0]), "+f"((d)[1]), "+f"((d)[2]), "+f"((d)[3]) \
                 : "r"(a0), "r"(a1), "r"(a2), "r"(a3), "r"(b0), "r"(b1))

// ---------------- kernel 0: W1 -> fp16, [k][n], with k16 permutation ----------------
// A is loaded as float4 at col 4*tig: logical ks (4t..4t+3) occupy mma k-slots
// (2t, 2t+1, 2t+8, 2t+9). B rows must be stored in the same slot order:
// logical k -> phys slot: t=(k&15)>>2, d=k&3 -> (k&~15) + 2t + (d&1) + (d>=2 ? 8 : 0)
__global__ void convB_kernel(const float* __restrict__ W1) {
    int idx = blockIdx.x * 256 + threadIdx.x;      // logical k*128 + n
    if (idx >= KD * NC) return;
    int k = idx >> 7, n = idx & 127;
    float w = W1[((long long)k + (n >= HD ? KD : 0)) * HD + (n & (HD - 1))];
    int kk = k & 15, t = kk >> 2, d = kk & 3;
    int phys = (k & ~15) + t * 2 + (d & 1) + ((d >= 2) ? 8 : 0);
    g_Bh[phys * NC + n] = __float2half_rn(w);
}

// ---------------- fused GEMM + pair epilogue ----------------
__global__ __launch_bounds__(256, 2)
void gemm_pair_kernel(const float* __restrict__ X,
                      const float* __restrict__ b1, const float* __restrict__ W2,
                      const float* __restrict__ b2, float* __restrict__ out) {
    extern __shared__ char smem[];
    const unsigned sb = smem_u32(smem);
    const int tid  = threadIdx.x;
    const int warp = tid >> 5;
    const int lane = tid & 31;
    const int wm   = warp & 3;      // 4 M-groups of 32 rows
    const int wn   = warp >> 2;     // 2 N-groups of 64 cols
    const int gid  = lane >> 2;     // 0..7
    const int tig  = lane & 3;      // 0..3
    const long long tile = blockIdx.x;

    if (tid < HD) {
        ((float*)(smem + OFF_SB1))[tid] = b1[tid];
        ((float*)(smem + OFF_SW2))[tid] = W2[tid];
    }
    if (tid == 0) ((float*)(smem + OFF_SB2))[0] = b2[0];

    // ---- A row pointers: 4 rows per thread (r, r+8, r+16, r+24) ----
    const float* xp[4];
    {
        long long r0 = tile * RPC + wm * 32 + gid;
        #pragma unroll
        for (int q = 0; q < 4; q++) {
            long long rr = r0 + q * 8;
            if (rr >= MROWS) rr = MROWS - 1;       // tail clamp (rows unused)
            xp[q] = X + rr * KD + 4 * tig;
        }
    }

    // ---- B cp.async coordinates ----
    const int bk = tid >> 3;                 // 0..31 (phys k row in chunk)
    const int bg = tid & 7;
    const unsigned bdst0 = (unsigned)(bk * BROW + bg * 16);
    const __half* bsrc = g_Bh + bk * NC + bg * 8;

    // ---- ldmatrix lane address (within stage) ----
    const unsigned sel   = lane >> 3;
    const unsigned rowin = lane & 7;
    const unsigned ldm_l = ((sel & 1) * 8 + rowin) * BROW + (wn * 64 + (sel >> 1) * 8) * 2;

    float acc[2][8][4];
    #pragma unroll
    for (int i = 0; i < 2; i++)
        #pragma unroll
        for (int j = 0; j < 8; j++)
            #pragma unroll
            for (int q = 0; q < 4; q++) acc[i][j][q] = 0.0f;

    float4 Abuf[4];
    auto loadA = [&](int h) {   // k16 half h (0..31): float4 per row
        Abuf[0] = *(const float4*)(xp[0] + h * 16);
        Abuf[1] = *(const float4*)(xp[1] + h * 16);
        Abuf[2] = *(const float4*)(xp[2] + h * 16);
        Abuf[3] = *(const float4*)(xp[3] + h * 16);
    };
    unsigned Ar[8];             // (a0,a1,a2,a3) x 2 i-frags
    auto cvtA = [&]() {
        #pragma unroll
        for (int q = 0; q < 4; q++) {
            __half2 t0 = __floats2half2_rn(Abuf[q].x, Abuf[q].y);
            __half2 t1 = __floats2half2_rn(Abuf[q].z, Abuf[q].w);
            // q=0: i0 a0/a2 ; q=1: i0 a1/a3 ; q=2: i1 a0/a2 ; q=3: i1 a1/a3
            Ar[(q >> 1) * 4 + (q & 1)]     = *(unsigned*)&t0;
            Ar[(q >> 1) * 4 + (q & 1) + 2] = *(unsigned*)&t1;
        }
    };

    // ---- prologue: stage chunk 0, load A half 0 ----
    cp16(sb + OFF_BSTG + bdst0,       bsrc);
    cp16(sb + OFF_BSTG + bdst0 + 128, bsrc + 64);
    CP_COMMIT();
    loadA(0);
    CP_WAIT0();
    __syncthreads();

    // ---- main loop over 16 chunks of k=32 ----
    #pragma unroll 1
    for (int it = 0; it < NCHUNK; ++it) {
        const unsigned stg = sb + OFF_BSTG + (it & 1) * STAGE_SZ;

        if (it + 1 < NCHUNK) {
            const unsigned nstg = sb + OFF_BSTG + ((it + 1) & 1) * STAGE_SZ;
            const __half* src = bsrc + (it + 1) * 32 * NC;
            cp16(nstg + bdst0,       src);
            cp16(nstg + bdst0 + 128, src + 64);
            CP_COMMIT();
        }

        #pragma unroll
        for (int h = 0; h < 2; ++h) {
            cvtA();
            if (it * 2 + h + 1 < 32) loadA(it * 2 + h + 1);   // prefetch next half

            unsigned bfr[16];
            const unsigned ab = stg + ldm_l + (unsigned)h * (16 * BROW);
            #pragma unroll
            for (int jj = 0; jj < 4; jj++)
                LDMX4T(bfr[jj * 4 + 0], bfr[jj * 4 + 1], bfr[jj * 4 + 2], bfr[jj * 4 + 3],
                       ab + jj * 32);

            #pragma unroll
            for (int i = 0; i < 2; i++)
                #pragma unroll
                for (int j = 0; j < 8; j++)
                    MMA16816(acc[i][j], Ar[i * 4 + 0], Ar[i * 4 + 1], Ar[i * 4 + 2], Ar[i * 4 + 3],
                             bfr[2 * j], bfr[2 * j + 1]);
        }
        CP_WAIT0();
        __syncthreads();
    }

    // ---- epilogue: acc -> sp[128][130] ----
    float* sp = (float*)(smem + OFF_SP);
    #pragma unroll
    for (int i = 0; i < 2; i++)
        #pragma unroll
        for (int j = 0; j < 8; j++) {
            int r = wm * 32 + i * 16 + gid;
            int c = wn * 64 + j * 8 + 2 * tig;
            *(float2*)(sp + r * SP_STRIDE + c)       = make_float2(acc[i][j][0], acc[i][j][1]);
            *(float2*)(sp + (r + 8) * SP_STRIDE + c) = make_float2(acc[i][j][2], acc[i][j][3]);
        }
    __syncthreads();

    // ---- pair compute ----
    const int nb = (int)min((long long)BPC, (long long)NBATCH - tile * BPC);
    float* vbuf = (float*)(smem + OFF_VBUF);
    const float* ssb1 = (const float*)(smem + OFF_SB1);
    const float* ssw2 = (const float*)(smem + OFF_SW2);
    const float bias2 = ((const float*)(smem + OFF_SB2))[0];

    for (int p = tid; p < nb * 45; p += 256) {
        int bb = p / 45, q = p - bb * 45;
        const float* pi = sp + (bb * NNODE + c_I[q]) * SP_STRIDE;        // pa
        const float* pj = sp + (bb * NNODE + c_J[q]) * SP_STRIDE + HD;   // pb
        float a2 = 0.0f;
        #pragma unroll
        for (int h = 0; h < HD; h++)
            a2 = fmaf(fmaxf(pi[h] + pj[h] + ssb1[h], 0.0f), ssw2[h], a2);
        vbuf[p] = a2 + bias2;
    }
    __syncthreads();

    // ---- symmetric scatter ----
    for (int o = tid; o < nb * 100; o += 256) {
        int bb = o / 100, cell = o - bb * 100;
        int n1 = cell / 10, n2 = cell % 10;
        float val = 0.0f;
        if (n1 != n2) {
            int i = n1 < n2 ? n1 : n2;
            int j = n1 < n2 ? n2 : n1;
            val = vbuf[bb * 45 + 9 * i - (i * (i - 1)) / 2 + (j - i - 1)];
        }
        out[(tile * BPC + bb) * 100 + cell] = val;
    }
}

extern "C" void kernel_launch(void* const* d_in, const int* in_sizes, int n_in,
                              void* d_out, int out_size) {
    const float* X  = (const float*)d_in[0];
    const float* W1 = (const float*)d_in[1];
    const float* b1 = (const float*)d_in[2];
    const float* W2 = (const float*)d_in[3];
    const float* b2 = (const float*)d_in[4];
    float* out = (float*)d_out;

    cudaFuncSetAttribute(gemm_pair_kernel,
                         cudaFuncAttributeMaxDynamicSharedMemorySize, SMEM_BYTES);

    convB_kernel<<<(KD * NC + 255) / 256, 256>>>(W1);
    gemm_pair_kernel<<<NCTA, 256, SMEM_BYTES>>>(X, b1, W2, b2, out);
}